// round 17
// baseline (speedup 1.0000x reference)
#include <cuda_runtime.h>
#include <cuda_bf16.h>
#include <math.h>
#include <cstdint>

#define BB 64
#define TT 384
#define DD 512

// ---------------------------------------------------------------------------
// Device scratch
// ---------------------------------------------------------------------------
__device__ float g_cost[BB][TT][TT];   // fp32 cost matrix
__device__ float g_dist[BB];

__device__ __forceinline__ uint32_t smem_u32(const void* p) {
    uint32_t a;
    asm("{ .reg .u64 t; cvta.to.shared.u64 t, %1; cvt.u32.u64 %0, t; }" : "=r"(a) : "l"(p));
    return a;
}
__device__ __forceinline__ uint32_t pack_bf16(float x, float y) {
    __nv_bfloat162 h = __floats2bfloat162_rn(x, y);
    return *reinterpret_cast<uint32_t*>(&h);
}
// SW32 swizzle for 32-byte rows: XOR 16B-slot bit (bit4) with row bit2 (bit7)
#define SWZ32(off) ((off) ^ (((off) >> 3) & 0x10))

__device__ __forceinline__ void ldmatrix_x4(uint32_t& r0, uint32_t& r1,
                                            uint32_t& r2, uint32_t& r3, uint32_t addr) {
    asm volatile("ldmatrix.sync.aligned.m8n8.x4.shared.b16 {%0,%1,%2,%3}, [%4];"
                 : "=r"(r0), "=r"(r1), "=r"(r2), "=r"(r3) : "r"(addr));
}
__device__ __forceinline__ void mma_bf16(float* c, const uint32_t* a, const uint32_t* b) {
    asm volatile("mma.sync.aligned.m16n8k16.row.col.f32.bf16.bf16.f32 "
                 "{%0,%1,%2,%3}, {%4,%5,%6,%7}, {%8,%9}, {%0,%1,%2,%3};"
                 : "+f"(c[0]), "+f"(c[1]), "+f"(c[2]), "+f"(c[3])
                 : "r"(a[0]), "r"(a[1]), "r"(a[2]), "r"(a[3]), "r"(b[0]), "r"(b[1]));
}

// ---------------------------------------------------------------------------
// Stage 1: bf16 HMMA cost GEMM, BK=16, FOUR-stage smem ring.
// Per iter c: MMA(stage c%4) | bar | STS(chunk c+4 -> stage c%4) | LDG(chunk c+6).
// LDG->STS gap = 2 periods, STS->LDSM gap = 4 periods: DRAM latency hidden.
// 128x128 tile/CTA, 8 warps (2m x 4n), norms fused into staging.
// ---------------------------------------------------------------------------
__global__ __launch_bounds__(256)
void cost_hmma_kernel(const float* __restrict__ pred, const float* __restrict__ targ) {
    __shared__ __align__(1024) unsigned char sA[4][128 * 32];  // 4KB per stage
    __shared__ __align__(1024) unsigned char sB[4][128 * 32];
    __shared__ float s_pna[128][2], s_pnb[128][2];

    const int b  = blockIdx.z;
    const int i0 = blockIdx.y * 128;
    const int j0 = blockIdx.x * 128;
    const int tid  = threadIdx.x;
    const int wid  = tid >> 5;
    const int lane = tid & 31;
    const int moff = (wid >> 2) * 64;
    const int noff = (wid & 3) * 32;

    // global mapping: thread -> (row = tid>>1, 8-float half of each 16-col chunk)
    const int lrow = tid >> 1;
    const int half = tid & 1;
    const float* Ag = pred + (size_t)b * TT * DD + (size_t)(i0 + lrow) * DD + half * 8;
    const float* Bg = targ + (size_t)b * TT * DD + (size_t)(j0 + lrow) * DD + half * 8;
    const uint32_t dst = (uint32_t)lrow * 32 + half * 16;   // byte offset in stage

    // ldmatrix lane-address components (BK=16: 32B rows)
    const int quad = lane >> 3;
    const int r8   = lane & 7;
    const int a_mrow_base = moff + (quad & 1) * 8 + r8;
    const int a_kb        = (quad >> 1) * 16;
    const int b_nrow_base = noff + (quad >> 1) * 8 + r8;
    const int b_kb        = (quad & 1) * 16;

    float acc[4][4][4];
#pragma unroll
    for (int mi = 0; mi < 4; mi++)
#pragma unroll
        for (int ni = 0; ni < 4; ni++)
#pragma unroll
            for (int r = 0; r < 4; r++) acc[mi][ni][r] = 0.f;

    float na_part = 0.f, nb_part = 0.f;
    float4 avb[2][2], bvb[2][2];   // 2 LDG staging buffers x 2 float4 per matrix

    auto ldg_chunk = [&](int k, int p) {
        const float4* a4 = (const float4*)(Ag + k * 16);
        const float4* b4 = (const float4*)(Bg + k * 16);
        avb[p][0] = a4[0]; avb[p][1] = a4[1];
        bvb[p][0] = b4[0]; bvb[p][1] = b4[1];
#pragma unroll
        for (int q = 0; q < 2; q++) {
            na_part += avb[p][q].x * avb[p][q].x + avb[p][q].y * avb[p][q].y
                     + avb[p][q].z * avb[p][q].z + avb[p][q].w * avb[p][q].w;
            nb_part += bvb[p][q].x * bvb[p][q].x + bvb[p][q].y * bvb[p][q].y
                     + bvb[p][q].z * bvb[p][q].z + bvb[p][q].w * bvb[p][q].w;
        }
    };
    auto sts_chunk = [&](int stage, int p) {
        uint4 pa, pb;
        pa.x = pack_bf16(avb[p][0].x, avb[p][0].y); pa.y = pack_bf16(avb[p][0].z, avb[p][0].w);
        pa.z = pack_bf16(avb[p][1].x, avb[p][1].y); pa.w = pack_bf16(avb[p][1].z, avb[p][1].w);
        pb.x = pack_bf16(bvb[p][0].x, bvb[p][0].y); pb.y = pack_bf16(bvb[p][0].z, bvb[p][0].w);
        pb.z = pack_bf16(bvb[p][1].x, bvb[p][1].y); pb.w = pack_bf16(bvb[p][1].z, bvb[p][1].w);
        uint32_t o = SWZ32(dst);
        *(uint4*)(sA[stage] + o) = pa;
        *(uint4*)(sB[stage] + o) = pb;
    };

    // prologue: stages 0..3 <- chunks 0..3; buffers <- chunks 4,5
    ldg_chunk(0, 0); ldg_chunk(1, 1);
    sts_chunk(0, 0); sts_chunk(1, 1);
    ldg_chunk(2, 0); ldg_chunk(3, 1);
    sts_chunk(2, 0); sts_chunk(3, 1);
    ldg_chunk(4, 0); ldg_chunk(5, 1);
    __syncthreads();

    for (int c = 0; c < 32; c++) {       // 32 chunks of BK=16
        const uint32_t sAb = smem_u32(sA[c & 3]);
        const uint32_t sBb = smem_u32(sB[c & 3]);
        uint32_t afr[4][4], bfr[2][4];
#pragma unroll
        for (int mi = 0; mi < 4; mi++) {
            uint32_t addr = sAb + SWZ32((uint32_t)(a_mrow_base + mi * 16) * 32 + (uint32_t)a_kb);
            ldmatrix_x4(afr[mi][0], afr[mi][1], afr[mi][2], afr[mi][3], addr);
        }
#pragma unroll
        for (int np = 0; np < 2; np++) {
            uint32_t addr = sBb + SWZ32((uint32_t)(b_nrow_base + np * 16) * 32 + (uint32_t)b_kb);
            ldmatrix_x4(bfr[np][0], bfr[np][1], bfr[np][2], bfr[np][3], addr);
        }
#pragma unroll
        for (int mi = 0; mi < 4; mi++)
#pragma unroll
            for (int ni = 0; ni < 4; ni++)
                mma_bf16(acc[mi][ni], afr[mi], &bfr[ni >> 1][(ni & 1) * 2]);

        __syncthreads();                 // stage c%4 fully read by all warps

        if (c + 4 < 32) sts_chunk(c & 3, c & 1);     // chunk c+4 -> freed stage
        if (c + 6 < 32) ldg_chunk(c + 6, c & 1);     // refill buffer (2-period gap)
    }

    s_pna[lrow][half] = na_part;
    s_pnb[lrow][half] = nb_part;
    __syncthreads();

    // epilogue: cost = sqrt(max(na + nb - 2*dot, 0)), fp32 stores
    const int g  = lane >> 2;
    const int cp = (lane & 3) * 2;
#pragma unroll
    for (int mi = 0; mi < 4; mi++) {
#pragma unroll
        for (int half_m = 0; half_m < 2; half_m++) {
            int mrow = moff + mi * 16 + half_m * 8 + g;
            float na = s_pna[mrow][0] + s_pna[mrow][1];
            float* grow = &g_cost[b][i0 + mrow][j0];
#pragma unroll
            for (int ni = 0; ni < 4; ni++) {
                int ncol = noff + ni * 8 + cp;
                float nb0 = s_pnb[ncol][0]     + s_pnb[ncol][1];
                float nb1 = s_pnb[ncol + 1][0] + s_pnb[ncol + 1][1];
                float d0 = acc[mi][ni][half_m * 2 + 0];
                float d1 = acc[mi][ni][half_m * 2 + 1];
                float2 o;
                o.x = sqrtf(fmaxf(na + nb0 - 2.f * d0, 0.f));
                o.y = sqrtf(fmaxf(na + nb1 - 2.f * d1, 0.f));
                *(float2*)(grow + ncol) = o;
            }
        }
    }
}

// ---------------------------------------------------------------------------
// Stage 2: DTW warp pipeline, CH=4, SMEM ring with DEPTH-2 prefetch:
// step s loads step s+2's rows into ring slot (s+2)%3 (LDG->STS, same lane),
// compute reads slot s%3 via LDS. No register buffers, no rotation.
// ---------------------------------------------------------------------------
#define CH 4
#define NCH (TT / CH)          // 96 row-chunks
#define NSTEPS (NCH + 31)      // 127

__global__ __launch_bounds__(32) void dtw_kernel() {
    const int b = blockIdx.x;
    const int lane = threadIdx.x;
    const float INF = __int_as_float(0x7f800000);
    const float* __restrict__ cb = &g_cost[b][0][0];

    // ring[slot][lane][ii*3+q]; 13th float4 pads stride to 208B (conflict-free)
    __shared__ float4 ring[3][32][13];

    float t[12], right[CH], cornerSave = INF;
#pragma unroll
    for (int j = 0; j < 12; j++) t[j] = INF;
#pragma unroll
    for (int i = 0; i < CH; i++) right[i] = INF;

    // prologue: fill slots 0 and 1 (steps 0 and 1)
#pragma unroll
    for (int pre = 0; pre < 2; pre++) {
        int rn = pre - lane;
        if (rn >= 0 && rn < NCH) {
            const float* rp = cb + (size_t)rn * CH * TT + lane * 12;
#pragma unroll
            for (int ii = 0; ii < CH; ii++) {
                const float4* p4 = (const float4*)(rp + (size_t)ii * TT);
#pragma unroll
                for (int q = 0; q < 3; q++) ring[pre][lane][ii * 3 + q] = p4[q];
            }
        }
    }

    for (int s = 0; s < NSTEPS; s++) {
        // 1) prefetch step s+2 into slot (s+2)%3 (same-lane write, no sync needed)
        int rn = s + 2 - lane;
        if (rn >= 0 && rn < NCH) {
            const float* rp = cb + (size_t)rn * CH * TT + lane * 12;
            float4* dstp = ring[(s + 2) % 3][lane];
#pragma unroll
            for (int ii = 0; ii < CH; ii++) {
                const float4* p4 = (const float4*)(rp + (size_t)ii * TT);
#pragma unroll
                for (int q = 0; q < 3; q++) dstp[ii * 3 + q] = p4[q];
            }
        }

        // 2) neighbor handoff
        float lv[CH];
#pragma unroll
        for (int i = 0; i < CH; i++) lv[i] = __shfl_up_sync(0xffffffffu, right[i], 1);
        float cornerIn = __shfl_up_sync(0xffffffffu, cornerSave, 1);
        cornerSave = right[CH - 1];
        int r = s - lane;
        if (lane == 0) {
#pragma unroll
            for (int i = 0; i < CH; i++) lv[i] = INF;
            cornerIn = (r == 0) ? 0.f : INF;
        }

        // 3) compute step s from ring slot s%3
        if (r >= 0 && r < NCH) {
            const float4* src = ring[s % 3][lane];
#pragma unroll
            for (int ii = 0; ii < CH; ii++) {
                float4 q0 = src[ii * 3 + 0], q1 = src[ii * 3 + 1], q2 = src[ii * 3 + 2];
                float cst[12] = {q0.x, q0.y, q0.z, q0.w, q1.x, q1.y, q1.z, q1.w,
                                 q2.x, q2.y, q2.z, q2.w};
                float m[12];
                m[0] = fminf(t[0], (ii == 0) ? cornerIn : lv[ii - 1]);
#pragma unroll
                for (int jj = 1; jj < 12; jj++) m[jj] = fminf(t[jj], t[jj - 1]);
                float cl = lv[ii];
#pragma unroll
                for (int jj = 0; jj < 12; jj++) {
                    float v = cst[jj] + fminf(m[jj], cl);
                    t[jj] = v;
                    cl = v;
                }
                right[ii] = cl;
            }
        }
    }
    if (lane == 31) g_dist[b] = right[CH - 1];
}

// ---------------------------------------------------------------------------
// Stage 3: mean — unchanged
// ---------------------------------------------------------------------------
__global__ void reduce_kernel(float* __restrict__ out) {
    int lane = threadIdx.x;
    float s = g_dist[lane] + g_dist[lane + 32];
#pragma unroll
    for (int o = 16; o > 0; o >>= 1) s += __shfl_xor_sync(0xffffffffu, s, o);
    if (lane == 0) out[0] = s * (1.f / BB);
}

// ---------------------------------------------------------------------------
extern "C" void kernel_launch(void* const* d_in, const int* in_sizes, int n_in,
                              void* d_out, int out_size) {
    const float* pred = (const float*)d_in[0];
    const float* targ = (const float*)d_in[1];
    float* out = (float*)d_out;

    cost_hmma_kernel<<<dim3(TT / 128, TT / 128, BB), 256>>>(pred, targ);
    dtw_kernel<<<BB, 32>>>();
    reduce_kernel<<<1, 32>>>(out);
}